// round 9
// baseline (speedup 1.0000x reference)
#include <cuda_runtime.h>
#include <cuda_fp16.h>
#include <cstdint>

// Problem constants: B=8, N=8192, D=256, K=3
#define BB 8
#define NN 8192
#define DD 256
#define KK 3
#define TOKENS (BB * NN)            // 65536

#define CTA_M 128                   // tokens per CTA
#define CTA_N 64                    // output dims per CTA (4 quarters of 256)
#define KC 32                       // contract chunk (2 k16 steps)
#define NCHUNK 24                   // 768 / 32
#define S_STRIDE 40                 // halves; conflict-free for all fragment patterns

struct Tap { int fi, ci; float cf, cc; };

// __device__ scratch (no allocation allowed)
__device__ Tap    d_taps[TOKENS * KK];        // 3 MB
__device__ __half d_Wh[DD * KK * DD];         // 384 KB: d_Wh[n][tap*256+e]

// fp16-accumulate MMA: C/D packed f16x2 (2 regs)
__device__ __forceinline__ void mma_f16acc(uint32_t* c, const uint32_t* a,
                                           uint32_t b0, uint32_t b1) {
    asm volatile(
        "mma.sync.aligned.m16n8k16.row.col.f16.f16.f16.f16 "
        "{%0,%1}, {%2,%3,%4,%5}, {%6,%7}, {%0,%1};"
        : "+r"(c[0]), "+r"(c[1])
        : "r"(a[0]), "r"(a[1]), "r"(a[2]), "r"(a[3]), "r"(b0), "r"(b1));
}

// ---------------------------------------------------------------------------
// Kernel 1: B matrix build. d_Wh[n*768 + tap*256 + e] = half(weight[n][e][tap]).
// ---------------------------------------------------------------------------
__global__ void build_b_kernel(const float* __restrict__ w) {
    int idx = blockIdx.x * blockDim.x + threadIdx.x;   // (n, e)
    if (idx >= DD * DD) return;
    int n = idx >> 8, e = idx & 255;
#pragma unroll
    for (int tap = 0; tap < KK; ++tap)
        d_Wh[n * (KK * DD) + tap * DD + e] = __float2half(w[(n * DD + e) * KK + tap]);
}

// ---------------------------------------------------------------------------
// Kernel 2: per-token tap parameters (one warp per token). Proven from R6/R7.
// ---------------------------------------------------------------------------
__global__ void compute_taps_kernel(const float* __restrict__ x,
                                    const float* __restrict__ ow,
                                    const float* __restrict__ mw) {
    int gw   = (blockIdx.x * blockDim.x + threadIdx.x) >> 5;
    int lane = threadIdx.x & 31;
    if (gw >= TOKENS) return;

    const float* xr = x + (long long)gw * DD;
    float s0 = 0.f, s1 = 0.f, s2 = 0.f, s3 = 0.f, s4 = 0.f, s5 = 0.f;
#pragma unroll
    for (int i = 0; i < DD / 32; ++i) {
        int e = lane + (i << 5);
        float v = xr[e];
        s0 += v * __ldg(ow + e);
        s1 += v * __ldg(ow + DD + e);
        s2 += v * __ldg(ow + 2 * DD + e);
        s3 += v * __ldg(mw + e);
        s4 += v * __ldg(mw + DD + e);
        s5 += v * __ldg(mw + 2 * DD + e);
    }
#pragma unroll
    for (int off = 16; off > 0; off >>= 1) {
        s0 += __shfl_xor_sync(0xffffffffu, s0, off);
        s1 += __shfl_xor_sync(0xffffffffu, s1, off);
        s2 += __shfl_xor_sync(0xffffffffu, s2, off);
        s3 += __shfl_xor_sync(0xffffffffu, s3, off);
        s4 += __shfl_xor_sync(0xffffffffu, s4, off);
        s5 += __shfl_xor_sync(0xffffffffu, s5, off);
    }
    if (lane == 0) {
        int n = gw & (NN - 1);
        float offs[3] = { s0, s1, s2 };
        float mraw[3] = { s3, s4, s5 };
#pragma unroll
        for (int k = 0; k < KK; ++k) {
            float pos = (float)(n + k - 1) + offs[k];
            float m   = 1.0f / (1.0f + expf(-mraw[k]));
            bool valid = (pos >= 0.0f) && (pos < (float)NN);
            float ff = floorf(pos);
            ff = fminf(fmaxf(ff, 0.0f), (float)(NN - 1));
            int fi = (int)ff;
            int ci = min(fi + 1, NN - 1);
            float wc = pos - ff;
            float coef = valid ? m : 0.0f;
            Tap t;
            t.fi = fi; t.ci = ci;
            t.cf = coef * (1.0f - wc);
            t.cc = coef * wc;
            d_taps[gw * KK + k] = t;
        }
    }
}

// ---------------------------------------------------------------------------
// Kernel 3: fused gather + fp16 mma.sync with fp16 accumulate + per-chunk
// fp32 drain. CTA: 128 tokens x 64 outputs (4 n-quarters via grid).
// 8 warps = 4m x 2n; warp tile 32x32. Register prefetch overlaps MMAs.
// ---------------------------------------------------------------------------
__global__ __launch_bounds__(256, 2)
void gemm_mma_kernel(const float* __restrict__ x, float* __restrict__ out) {
    __shared__ __half As[CTA_M * S_STRIDE];   // [token][k_local]
    __shared__ __half Bs[CTA_N * S_STRIDE];   // [n_local][k_local]
    __shared__ Tap    s_taps[CTA_M * KK];

    const int tid  = threadIdx.x;
    const int wid  = tid >> 5;
    const int lane = tid & 31;
    const int wm   = wid & 3;         // warp row (4 m-tiles of 32)
    const int wn   = wid >> 2;        // warp col (2 n-tiles of 32)
    const int grp  = lane >> 2;       // 0..7
    const int tg   = lane & 3;        // 0..3

    const int tile = blockIdx.x >> 2;
    const int nq   = blockIdx.x & 3;  // n-quarter (64 cols)
    const int tok0 = tile * CTA_M;
    const int b    = tok0 >> 13;
    const float* xb = x + (size_t)b * NN * DD;

    // loader roles
    const int a_tok = tid >> 1;       // 0..127, 2 threads/token (16 floats each)
    const int ah    = tid & 1;
    const int b_col = tid >> 2;       // 0..63
    const int b_kq  = tid & 3;        // 8 halves each

    for (int i = tid; i < CTA_M * KK; i += 256) s_taps[i] = d_taps[tok0 * KK + i];
    __syncthreads();

    float    acc[2][4][4];            // fp32 master accumulators
    uint32_t acc16[2][4][2];          // fp16 packed accumulators (per chunk)
#pragma unroll
    for (int mi = 0; mi < 2; ++mi)
#pragma unroll
        for (int ni = 0; ni < 4; ++ni) {
#pragma unroll
            for (int j = 0; j < 4; ++j) acc[mi][ni][j] = 0.0f;
            acc16[mi][ni][0] = 0u; acc16[mi][ni][1] = 0u;
        }

    float4 pa[4];     // prefetched interpolated A (16 f32)
    uint4  pb;        // prefetched B (8 halves)

    const __half* whb = d_Wh + (size_t)(nq * CTA_N + b_col) * (KK * DD) + b_kq * 8;

    // prologue: chunk 0
    {
        Tap t = s_taps[a_tok * KK + 0];
        const float4* pf = (const float4*)(xb + t.fi * DD + ah * 16);
        const float4* pc = (const float4*)(xb + t.ci * DD + ah * 16);
#pragma unroll
        for (int j = 0; j < 4; ++j) {
            float4 vf = pf[j], vc = pc[j];
            pa[j].x = fmaf(t.cf, vf.x, t.cc * vc.x);
            pa[j].y = fmaf(t.cf, vf.y, t.cc * vc.y);
            pa[j].z = fmaf(t.cf, vf.z, t.cc * vc.z);
            pa[j].w = fmaf(t.cf, vf.w, t.cc * vc.w);
        }
        pb = *(const uint4*)whb;
    }

    for (int c = 0; c < NCHUNK; ++c) {
        __syncthreads();   // previous chunk fully consumed

        // store prefetched tiles (A converted f32 -> half2 here)
        {
            uint4 ha;
            __half2* hp = (__half2*)&ha;
            hp[0] = __floats2half2_rn(pa[0].x, pa[0].y);
            hp[1] = __floats2half2_rn(pa[0].z, pa[0].w);
            hp[2] = __floats2half2_rn(pa[1].x, pa[1].y);
            hp[3] = __floats2half2_rn(pa[1].z, pa[1].w);
            *(uint4*)&As[a_tok * S_STRIDE + ah * 16] = ha;
            hp[0] = __floats2half2_rn(pa[2].x, pa[2].y);
            hp[1] = __floats2half2_rn(pa[2].z, pa[2].w);
            hp[2] = __floats2half2_rn(pa[3].x, pa[3].y);
            hp[3] = __floats2half2_rn(pa[3].z, pa[3].w);
            *(uint4*)&As[a_tok * S_STRIDE + ah * 16 + 8] = ha;
            *(uint4*)&Bs[b_col * S_STRIDE + b_kq * 8] = pb;
        }
        __syncthreads();   // tiles visible

        // prefetch chunk c+1 (overlaps MMA below)
        if (c + 1 < NCHUNK) {
            const int cn  = c + 1;
            const int tap = cn >> 3;
            const int e0  = (cn & 7) << 5;
            Tap t = s_taps[a_tok * KK + tap];
            const float4* pf = (const float4*)(xb + t.fi * DD + e0 + ah * 16);
            const float4* pc = (const float4*)(xb + t.ci * DD + e0 + ah * 16);
#pragma unroll
            for (int j = 0; j < 4; ++j) {
                float4 vf = pf[j], vc = pc[j];
                pa[j].x = fmaf(t.cf, vf.x, t.cc * vc.x);
                pa[j].y = fmaf(t.cf, vf.y, t.cc * vc.y);
                pa[j].z = fmaf(t.cf, vf.z, t.cc * vc.z);
                pa[j].w = fmaf(t.cf, vf.w, t.cc * vc.w);
            }
            pb = *(const uint4*)(whb + cn * KC);
        }

        // MMA over current chunk: 2 k16 steps, fp16 accumulate
#pragma unroll
        for (int ks = 0; ks < 2; ++ks) {
            const int k0 = ks * 16;
            uint32_t afr[2][4];
#pragma unroll
            for (int mi = 0; mi < 2; ++mi) {
                int row = wm * 32 + mi * 16;
                afr[mi][0] = *(const uint32_t*)&As[(row + grp    ) * S_STRIDE + k0 + 2 * tg    ];
                afr[mi][1] = *(const uint32_t*)&As[(row + grp + 8) * S_STRIDE + k0 + 2 * tg    ];
                afr[mi][2] = *(const uint32_t*)&As[(row + grp    ) * S_STRIDE + k0 + 2 * tg + 8];
                afr[mi][3] = *(const uint32_t*)&As[(row + grp + 8) * S_STRIDE + k0 + 2 * tg + 8];
            }
#pragma unroll
            for (int ni = 0; ni < 4; ++ni) {
                int col = wn * 32 + ni * 8 + grp;
                uint32_t b0 = *(const uint32_t*)&Bs[col * S_STRIDE + k0 + 2 * tg    ];
                uint32_t b1 = *(const uint32_t*)&Bs[col * S_STRIDE + k0 + 2 * tg + 8];
                mma_f16acc(acc16[0][ni], afr[0], b0, b1);
                mma_f16acc(acc16[1][ni], afr[1], b0, b1);
            }
        }

        // drain fp16 accumulators into fp32 (keeps rounding error ~3e-4 total)
#pragma unroll
        for (int mi = 0; mi < 2; ++mi)
#pragma unroll
            for (int ni = 0; ni < 4; ++ni) {
                __half2 h0 = *reinterpret_cast<__half2*>(&acc16[mi][ni][0]);
                __half2 h1 = *reinterpret_cast<__half2*>(&acc16[mi][ni][1]);
                float2 f0 = __half22float2(h0);
                float2 f1 = __half22float2(h1);
                acc[mi][ni][0] += f0.x;
                acc[mi][ni][1] += f0.y;
                acc[mi][ni][2] += f1.x;
                acc[mi][ni][3] += f1.y;
                acc16[mi][ni][0] = 0u;
                acc16[mi][ni][1] = 0u;
            }
    }

    // epilogue: c0/c1 at (row, 2tg), c2/c3 at (row+8, 2tg)
#pragma unroll
    for (int mi = 0; mi < 2; ++mi) {
        size_t row = (size_t)tok0 + wm * 32 + mi * 16 + grp;
        float* op0 = out + row * DD + nq * CTA_N + wn * 32;
        float* op1 = op0 + 8 * DD;
#pragma unroll
        for (int ni = 0; ni < 4; ++ni) {
            int col = ni * 8 + tg * 2;
            float2 v0 = { acc[mi][ni][0], acc[mi][ni][1] };
            float2 v1 = { acc[mi][ni][2], acc[mi][ni][3] };
            *(float2*)(op0 + col) = v0;
            *(float2*)(op1 + col) = v1;
        }
    }
}

// ---------------------------------------------------------------------------
// Launch (graph-capturable: kernel launches only)
// ---------------------------------------------------------------------------
extern "C" void kernel_launch(void* const* d_in, const int* in_sizes, int n_in,
                              void* d_out, int out_size) {
    const float* x  = (const float*)d_in[0];
    const float* ow = (const float*)d_in[1];
    const float* mw = (const float*)d_in[2];
    const float* w  = (const float*)d_in[3];
    float* out = (float*)d_out;
    (void)in_sizes; (void)n_in; (void)out_size;

    build_b_kernel<<<(DD * DD + 255) / 256, 256>>>(w);
    compute_taps_kernel<<<TOKENS / 8, 256>>>(x, ow, mw);
    gemm_mma_kernel<<<(TOKENS / CTA_M) * 4, 256>>>(x, out);
}